// round 9
// baseline (speedup 1.0000x reference)
#include <cuda_runtime.h>
#include <math.h>

#define T_STEPS 256
#define BB      32
#define NI      28
#define NH      1024
#define NO      10
#define GRID    128
#define NTH     512
#define NW      16        // warps per CTA
#define KS      64        // j-slice per warp
#define IT      32        // rows (i) per CTA
#define NBT     4         // batch tiles
#define CB      16        // V columns per CTA (8 batches x {cos,sin})
#define TWO_PI_F 6.283185307179586f
#define INV_TWO_PI_F 0.15915494309189535f

typedef unsigned long long ull;

// ---- persistent device scratch ----
__device__ float d_P[(size_t)T_STEPS * NH * BB];    // [t][h][b]
__device__ float d_V[2][NBT][NH][CB];               // [ping][btile][j][col]
__device__ float d_state[BB * NH];                  // [b][h]
__device__ unsigned g_bar4[NBT * 32];               // per-group counters
__device__ unsigned g_bar;                          // final one-shot barrier

// packed f32x2 helpers
#define PACK2(d,a,b)   asm("mov.b64 %0, {%1, %2};" : "=l"(d) : "f"(a), "f"(b))
#define UNPACK2(a,b,v) asm("mov.b64 {%0, %1}, %2;" : "=f"(a), "=f"(b) : "l"(v))
#define FMA2(d,a,b,c)  asm("fma.rn.f32x2 %0, %1, %2, %3;" : "=l"(d) : "l"(a), "l"(b), "l"(c))
#define ADD2(d,a,b)    asm("add.rn.f32x2 %0, %1, %2;" : "=l"(d) : "l"(a), "l"(b))

// ---------------- prep ----------------
__global__ void prep_kernel(const float* __restrict__ x,
                            const float* __restrict__ Wi_w,
                            const float* __restrict__ Wi_b,
                            const float* __restrict__ omega) {
    const int bid = blockIdx.x;          // = t*BB + b
    const int t = bid >> 5;
    const int b = bid & 31;
    __shared__ float xs[NI];
    if (threadIdx.x < NI) xs[threadIdx.x] = x[(size_t)bid * NI + threadIdx.x];
    if (bid == 0) {
        if (threadIdx.x == 0) g_bar = 0u;
        if (threadIdx.x < NBT * 32) g_bar4[threadIdx.x] = 0u;
    }
    if (bid < (NBT * NH * CB) / 256) {
        const int idx = bid * 256 + threadIdx.x;
        ((float*)d_V)[idx] = (idx & 1) ? 0.0f : 1.0f;
    }
    __syncthreads();
#pragma unroll
    for (int k = 0; k < NH / 256; ++k) {
        const int h = threadIdx.x + k * 256;
        float acc = Wi_b[h] + omega[h];
        const float* wr = Wi_w + (size_t)h * NI;
#pragma unroll
        for (int i = 0; i < NI; ++i) acc = fmaf(xs[i], wr[i], acc);
        d_P[((size_t)t * NH + h) * BB + b] = acc;
    }
}

// ---------------- proven atomic+spin barrier ----------------
__device__ __forceinline__ void bar_on(unsigned* ctr, unsigned target) {
    __syncthreads();
    if (threadIdx.x == 0) {
        __threadfence();
        atomicAdd(ctr, 1u);
        while (*(volatile unsigned*)ctr < target) { }
        __threadfence();
    }
    __syncthreads();
}

// ---------------- persistent scan kernel ----------------
// smem: WhT [1024][32] (128KB) | Vs [1024][16] (64KB) | red ull[16][32][8] swizzled (32KB)
#define SMEM_FLOATS (NH*IT + NH*CB)
#define SMEM_BYTES  (SMEM_FLOATS*4 + NW*IT*8*8)

extern __shared__ float smem[];

__global__ void __launch_bounds__(NTH, 1)
scan_kernel(const float* __restrict__ Wh,
            const float* __restrict__ W_out,
            const float* __restrict__ b_out,
            float* __restrict__ out) {
    float* WhT = smem;                          // WhT[j*32 + r] = Wh[i0+r][j]
    float* Vs  = smem + NH * IT;                // Vs[j*16 + c]
    ull*   red = (ull*)(smem + SMEM_FLOATS);    // red[(w*32+row)*8 + ((cp+row)&7)]

    const int tid = threadIdx.x;
    const int cta = blockIdx.x;
    const int it  = cta >> 2;            // i-tile 0..31
    const int bt  = cta & 3;             // batch-tile 0..3
    const int i0  = it * IT;

    // one-time fill of WhT (coalesced global reads)
    for (int idx = tid; idx < NH * IT; idx += NTH) {
        const int r = idx >> 10, j = idx & 1023;
        WhT[j * IT + r] = Wh[(size_t)(i0 + r) * NH + j];
    }

    const int w  = tid >> 5;             // warp: j-slice [w*64, w*64+64)
    const int l  = tid & 31;
    const int jo = l >> 3;               // 0..3 : j-subslice [jo*16, jo*16+16) within warp slice
    const int rg = l & 7;                // 0..7 : rows rg*4 .. rg*4+3

    const int i_loc = (tid & 255) >> 3;  // 0..31 (update threads: tid<256)
    const int lb    = tid & 7;           // 0..7
    const int h     = i0 + i_loc;
    const int b     = bt * 8 + lb;

    float s = 0.0f, s_sin = 0.0f, s_cos = 1.0f;

    __syncthreads();

    int ping = 0;
    unsigned target = 0;

    for (int t = 0; t < T_STEPS; ++t) {
        float p = 0.0f;
        if (tid < 256) p = __ldg(&d_P[((size_t)t * NH + h) * BB + b]);

        // ---- per-warp stage of this warp's V slice (4KB) via cp.async ----
        {
            const char* src = (const char*)(&d_V[ping][bt][0][0]) + (size_t)w * 4096 + l * 16;
            unsigned dst = (unsigned)__cvta_generic_to_shared(Vs + w * KS * CB) + l * 16;
#pragma unroll
            for (int k = 0; k < 8; ++k)
                asm volatile("cp.async.cg.shared.global [%0], [%1], 16;"
                             :: "r"(dst + k * 512), "l"(src + k * 512));
            asm volatile("cp.async.commit_group;");
            asm volatile("cp.async.wait_group 0;");
        }
        __syncwarp();

        // ---- GEMM: lane tile 4 rows x 16 cols (8 colpairs) x 16 j, f32x2 ----
        ull acc[4][8];
#pragma unroll
        for (int r = 0; r < 4; ++r)
#pragma unroll
            for (int c = 0; c < 8; ++c) acc[r][c] = 0ull;

        const float* Wp = WhT + (w * KS + jo * 16) * IT + rg * 4;
        const float* Vp = Vs  + (w * KS + jo * 16) * CB;

#pragma unroll 4
        for (int jj = 0; jj < 16; ++jj) {
            const float4 wv = *(const float4*)Wp;               // Wh rows rg*4..+3
            const ulonglong2 va = *(const ulonglong2*)Vp;       // colpairs 0,1
            const ulonglong2 vb = *(const ulonglong2*)(Vp + 4); // colpairs 2,3
            const ulonglong2 vc = *(const ulonglong2*)(Vp + 8); // colpairs 4,5
            const ulonglong2 vd = *(const ulonglong2*)(Vp + 12);// colpairs 6,7
            ull w0, w1, w2, w3;
            PACK2(w0, wv.x, wv.x); PACK2(w1, wv.y, wv.y);
            PACK2(w2, wv.z, wv.z); PACK2(w3, wv.w, wv.w);
            FMA2(acc[0][0], w0, va.x, acc[0][0]); FMA2(acc[1][0], w1, va.x, acc[1][0]);
            FMA2(acc[2][0], w2, va.x, acc[2][0]); FMA2(acc[3][0], w3, va.x, acc[3][0]);
            FMA2(acc[0][1], w0, va.y, acc[0][1]); FMA2(acc[1][1], w1, va.y, acc[1][1]);
            FMA2(acc[2][1], w2, va.y, acc[2][1]); FMA2(acc[3][1], w3, va.y, acc[3][1]);
            FMA2(acc[0][2], w0, vb.x, acc[0][2]); FMA2(acc[1][2], w1, vb.x, acc[1][2]);
            FMA2(acc[2][2], w2, vb.x, acc[2][2]); FMA2(acc[3][2], w3, vb.x, acc[3][2]);
            FMA2(acc[0][3], w0, vb.y, acc[0][3]); FMA2(acc[1][3], w1, vb.y, acc[1][3]);
            FMA2(acc[2][3], w2, vb.y, acc[2][3]); FMA2(acc[3][3], w3, vb.y, acc[3][3]);
            FMA2(acc[0][4], w0, vc.x, acc[0][4]); FMA2(acc[1][4], w1, vc.x, acc[1][4]);
            FMA2(acc[2][4], w2, vc.x, acc[2][4]); FMA2(acc[3][4], w3, vc.x, acc[3][4]);
            FMA2(acc[0][5], w0, vc.y, acc[0][5]); FMA2(acc[1][5], w1, vc.y, acc[1][5]);
            FMA2(acc[2][5], w2, vc.y, acc[2][5]); FMA2(acc[3][5], w3, vc.y, acc[3][5]);
            FMA2(acc[0][6], w0, vd.x, acc[0][6]); FMA2(acc[1][6], w1, vd.x, acc[1][6]);
            FMA2(acc[2][6], w2, vd.x, acc[2][6]); FMA2(acc[3][6], w3, vd.x, acc[3][6]);
            FMA2(acc[0][7], w0, vd.y, acc[0][7]); FMA2(acc[1][7], w1, vd.y, acc[1][7]);
            FMA2(acc[2][7], w2, vd.y, acc[2][7]); FMA2(acc[3][7], w3, vd.y, acc[3][7]);
            Wp += IT;   // next j
            Vp += CB;
        }

        // ---- cross-jo reduce-scatter (2 shuffle rounds, proven pattern) ----
        {
            const bool hi3 = (l & 8) != 0;      // jo bit0
            ull keep0[8], keep1[8];
#pragma unroll
            for (int c = 0; c < 8; ++c) {
                ull s0 = hi3 ? acc[0][c] : acc[2][c];
                ull s1 = hi3 ? acc[1][c] : acc[3][c];
                ull r0 = __shfl_xor_sync(0xffffffffu, s0, 8);
                ull r1 = __shfl_xor_sync(0xffffffffu, s1, 8);
                ull k0 = hi3 ? acc[2][c] : acc[0][c];
                ull k1 = hi3 ? acc[3][c] : acc[1][c];
                ADD2(keep0[c], k0, r0);
                ADD2(keep1[c], k1, r1);
            }
            const bool hi4 = (l & 16) != 0;     // jo bit1
            const int rpo = ((l & 8) >> 2) | ((l & 16) >> 4);
            const int row = rg * 4 + rpo;
#pragma unroll
            for (int c = 0; c < 8; ++c) {
                ull sd = hi4 ? keep0[c] : keep1[c];
                ull rv = __shfl_xor_sync(0xffffffffu, sd, 16);
                ull kp = hi4 ? keep1[c] : keep0[c];
                ull fin; ADD2(fin, kp, rv);
                red[(w * IT + row) * 8 + ((c + row) & 7)] = fin;
            }
        }
        __syncthreads();

        if (tid < 256) {
            // ---- final 16-warp reduction: this thread's own (row, colpair) ----
            const int sw = (lb + i_loc) & 7;
            ull sacc = red[(0 * IT + i_loc) * 8 + sw];
#pragma unroll
            for (int ww = 1; ww < NW; ++ww)
                ADD2(sacc, sacc, red[(ww * IT + i_loc) * 8 + sw]);

            // ---- state update for (b, h) ----
            float Ccos, Csin;
            UNPACK2(Ccos, Csin, sacc);
            const float coup = s_sin * Ccos - s_cos * Csin;
            const float xv   = coup + p + s;
            const float k    = floorf(xv * INV_TWO_PI_F);
            float ns = fmaf(-TWO_PI_F, k, xv);
            if (ns < 0.0f) ns += TWO_PI_F;
            else if (ns >= TWO_PI_F) ns -= TWO_PI_F;
            s = ns;
            __sincosf(s, &s_sin, &s_cos);
            *(float2*)&d_V[ping ^ 1][bt][h][2 * lb] = make_float2(s_cos, s_sin);
        }
        ping ^= 1;

        // ---- group barrier: all 32 CTAs of this bt-group finished step t ----
        target += 32;
        bar_on(&g_bar4[bt * 32], target);
    }

    // ---- final state out + full-grid barrier + readout ----
    if (tid < 256) d_state[b * NH + h] = s;
    bar_on(&g_bar, GRID);

    if (cta == 0) {
        for (int pair = w; pair < BB * NO; pair += NW) {
            const int bb = pair / NO, oo = pair % NO;
            float acc = 0.0f;
            for (int hh = l; hh < NH; hh += 32)
                acc = fmaf(__ldcg(&d_state[bb * NH + hh]), W_out[(size_t)oo * NH + hh], acc);
#pragma unroll
            for (int off = 16; off; off >>= 1)
                acc += __shfl_down_sync(0xffffffffu, acc, off);
            if (l == 0) out[bb * NO + oo] = acc + b_out[oo];
        }
    }
}

extern "C" void kernel_launch(void* const* d_in, const int* in_sizes, int n_in,
                              void* d_out, int out_size) {
    const float* x     = (const float*)d_in[0];
    const float* Wi_w  = (const float*)d_in[1];
    const float* Wi_b  = (const float*)d_in[2];
    const float* Wh    = (const float*)d_in[3];
    const float* omega = (const float*)d_in[4];
    const float* W_out = (const float*)d_in[5];
    const float* b_out = (const float*)d_in[6];
    float* out = (float*)d_out;

    cudaFuncSetAttribute(scan_kernel, cudaFuncAttributeMaxDynamicSharedMemorySize, SMEM_BYTES);

    prep_kernel<<<T_STEPS * BB, 256>>>(x, Wi_w, Wi_b, omega);
    scan_kernel<<<GRID, NTH, SMEM_BYTES>>>(Wh, W_out, b_out, out);
}

// round 11
// speedup vs baseline: 1.0693x; 1.0693x over previous
#include <cuda_runtime.h>
#include <math.h>

#define T_STEPS 256
#define BB      32
#define NI      28
#define NH      1024
#define NO      10
#define GRID    128
#define NTH     256
#define NW      8         // warps per CTA
#define KS      128       // j-slice per warp
#define IT      32        // rows (i) per CTA
#define NBT     4         // batch tiles
#define CB      16        // V columns per CTA (8 batches x {cos,sin})
#define TWO_PI_F 6.283185307179586f
#define INV_TWO_PI_F 0.15915494309189535f

typedef unsigned long long ull;

// ---- persistent device scratch ----
__device__ float d_P[(size_t)T_STEPS * NH * BB];    // [t][h][b]
__device__ float d_V[2][NBT][NH][CB];               // [ping][btile][j][col]
__device__ float d_state[BB * NH];                  // [b][h]
__device__ int d_flags[NBT][32];                    // producer step counters (monotonic, RED-published)
__device__ unsigned g_bar;                          // final one-shot barrier

// packed f32x2 helpers
#define PACK2(d,a,b)   asm("mov.b64 %0, {%1, %2};" : "=l"(d) : "f"(a), "f"(b))
#define UNPACK2(a,b,v) asm("mov.b64 {%0, %1}, %2;" : "=f"(a), "=f"(b) : "l"(v))
#define FMA2(d,a,b,c)  asm("fma.rn.f32x2 %0, %1, %2, %3;" : "=l"(d) : "l"(a), "l"(b), "l"(c))
#define ADD2(d,a,b)    asm("add.rn.f32x2 %0, %1, %2;" : "=l"(d) : "l"(a), "l"(b))

// ---------------- prep ----------------
__global__ void prep_kernel(const float* __restrict__ x,
                            const float* __restrict__ Wi_w,
                            const float* __restrict__ Wi_b,
                            const float* __restrict__ omega) {
    const int bid = blockIdx.x;          // = t*BB + b
    const int t = bid >> 5;
    const int b = bid & 31;
    __shared__ float xs[NI];
    if (threadIdx.x < NI) xs[threadIdx.x] = x[(size_t)bid * NI + threadIdx.x];
    if (bid == 0) {
        if (threadIdx.x == 0) g_bar = 0u;
        if (threadIdx.x < NBT * 32) ((int*)d_flags)[threadIdx.x] = 0;
    }
    if (bid < (NBT * NH * CB) / 256) {
        const int idx = bid * 256 + threadIdx.x;
        ((float*)d_V)[idx] = (idx & 1) ? 0.0f : 1.0f;
    }
    __syncthreads();
#pragma unroll
    for (int k = 0; k < NH / 256; ++k) {
        const int h = threadIdx.x + k * 256;
        float acc = Wi_b[h] + omega[h];
        const float* wr = Wi_w + (size_t)h * NI;
#pragma unroll
        for (int i = 0; i < NI; ++i) acc = fmaf(xs[i], wr[i], acc);
        d_P[((size_t)t * NH + h) * BB + b] = acc;
    }
}

// ---------------- one-shot atomic barrier (final readout only) ----------------
__device__ __forceinline__ void bar_on(unsigned* ctr, unsigned target) {
    __syncthreads();
    if (threadIdx.x == 0) {
        __threadfence();
        atomicAdd(ctr, 1u);
        while (*(volatile unsigned*)ctr < target) { }
        __threadfence();
    }
    __syncthreads();
}

// ---------------- persistent scan kernel ----------------
// smem: WhT [1024][32] (128KB) | Vs [1024][16] (64KB) | red ull[8][32][9] padded (18KB)
#define RED_STRIDE 9
#define SMEM_FLOATS (NH*IT + NH*CB)
#define SMEM_BYTES  (SMEM_FLOATS*4 + NW*IT*RED_STRIDE*8)

extern __shared__ float smem[];

__global__ void __launch_bounds__(NTH, 1)
scan_kernel(const float* __restrict__ Wh,
            const float* __restrict__ W_out,
            const float* __restrict__ b_out,
            float* __restrict__ out) {
    float* WhT = smem;                          // WhT[j*32 + r] = Wh[i0+r][j]
    float* Vs  = smem + NH * IT;                // Vs[j*16 + c]
    ull*   red = (ull*)(smem + SMEM_FLOATS);    // red[(w*32+row)*9 + cp]

    const int tid = threadIdx.x;
    const int cta = blockIdx.x;
    const int it  = cta >> 2;            // i-tile 0..31
    const int bt  = cta & 3;             // batch-tile 0..3
    const int i0  = it * IT;

    // one-time fill of WhT (coalesced global reads)
    for (int idx = tid; idx < NH * IT; idx += NTH) {
        const int r = idx >> 10, j = idx & 1023;
        WhT[j * IT + r] = Wh[(size_t)(i0 + r) * NH + j];
    }

    const int w  = tid >> 5;             // warp: j-slice [w*128, w*128+128)
    const int l  = tid & 31;
    const int jo = l >> 3;               // 0..3 : j-subslice [jo*32, jo*32+32)
    const int rg = l & 7;                // 0..7 : rows rg*4 .. rg*4+3

    const int i_loc = tid >> 3;          // 0..31
    const int lb    = tid & 7;           // 0..7
    const int h     = i0 + i_loc;
    const int b     = bt * 8 + lb;

    // this warp's producer flag (4 producers: it = w*4 .. w*4+3)
    const int* myflag = &d_flags[bt][w * 4 + (l & 3)];

    float s = 0.0f, s_sin = 0.0f, s_cos = 1.0f;

    __syncthreads();

    int ping = 0;

    for (int t = 0; t < T_STEPS; ++t) {
        const float p = __ldg(&d_P[((size_t)t * NH + h) * BB + b]);

        // ---- warp-scoped wait: this warp's 4 producers reached step t ----
        {
            int f;
            asm volatile("ld.global.cg.b32 %0, [%1];" : "=r"(f) : "l"(myflag) : "memory");
            while (__any_sync(0xffffffffu, f < t)) {
                __nanosleep(40);
                asm volatile("ld.global.cg.b32 %0, [%1];" : "=r"(f) : "l"(myflag) : "memory");
            }
        }

        // ---- per-warp stage of this warp's V slice (8KB) into smem ----
        {
            const float4* src = (const float4*)(&d_V[ping][bt][0][0]) + w * 512;
            float4* dst = (float4*)(Vs + w * KS * CB);
            float4 tmp[8];
#pragma unroll
            for (int k = 0; k < 8; ++k) tmp[k] = __ldcg(src + l + k * 32);
#pragma unroll
            for (int k = 0; k < 8; ++k) dst[l + k * 32] = tmp[k];
#pragma unroll
            for (int k = 0; k < 8; ++k) tmp[k] = __ldcg(src + l + (k + 8) * 32);
#pragma unroll
            for (int k = 0; k < 8; ++k) dst[l + (k + 8) * 32] = tmp[k];
        }
        __syncwarp();

        // ---- GEMM: lane tile 4 rows x 16 cols (8 colpairs) x 32 j, f32x2 ----
        ull acc[4][8];
#pragma unroll
        for (int r = 0; r < 4; ++r)
#pragma unroll
            for (int c = 0; c < 8; ++c) acc[r][c] = 0ull;

        const float* Wp = WhT + (w * KS + jo * 32) * IT + rg * 4;
        const float* Vp = Vs  + (w * KS + jo * 32) * CB;

#pragma unroll 4
        for (int jj = 0; jj < 32; ++jj) {
            const float4 wv = *(const float4*)Wp;               // Wh rows rg*4..+3
            const ulonglong2 va = *(const ulonglong2*)Vp;       // colpairs 0,1
            const ulonglong2 vb = *(const ulonglong2*)(Vp + 4); // colpairs 2,3
            const ulonglong2 vc = *(const ulonglong2*)(Vp + 8); // colpairs 4,5
            const ulonglong2 vd = *(const ulonglong2*)(Vp + 12);// colpairs 6,7
            ull w0, w1, w2, w3;
            PACK2(w0, wv.x, wv.x); PACK2(w1, wv.y, wv.y);
            PACK2(w2, wv.z, wv.z); PACK2(w3, wv.w, wv.w);
            FMA2(acc[0][0], w0, va.x, acc[0][0]); FMA2(acc[1][0], w1, va.x, acc[1][0]);
            FMA2(acc[2][0], w2, va.x, acc[2][0]); FMA2(acc[3][0], w3, va.x, acc[3][0]);
            FMA2(acc[0][1], w0, va.y, acc[0][1]); FMA2(acc[1][1], w1, va.y, acc[1][1]);
            FMA2(acc[2][1], w2, va.y, acc[2][1]); FMA2(acc[3][1], w3, va.y, acc[3][1]);
            FMA2(acc[0][2], w0, vb.x, acc[0][2]); FMA2(acc[1][2], w1, vb.x, acc[1][2]);
            FMA2(acc[2][2], w2, vb.x, acc[2][2]); FMA2(acc[3][2], w3, vb.x, acc[3][2]);
            FMA2(acc[0][3], w0, vb.y, acc[0][3]); FMA2(acc[1][3], w1, vb.y, acc[1][3]);
            FMA2(acc[2][3], w2, vb.y, acc[2][3]); FMA2(acc[3][3], w3, vb.y, acc[3][3]);
            FMA2(acc[0][4], w0, vc.x, acc[0][4]); FMA2(acc[1][4], w1, vc.x, acc[1][4]);
            FMA2(acc[2][4], w2, vc.x, acc[2][4]); FMA2(acc[3][4], w3, vc.x, acc[3][4]);
            FMA2(acc[0][5], w0, vc.y, acc[0][5]); FMA2(acc[1][5], w1, vc.y, acc[1][5]);
            FMA2(acc[2][5], w2, vc.y, acc[2][5]); FMA2(acc[3][5], w3, vc.y, acc[3][5]);
            FMA2(acc[0][6], w0, vd.x, acc[0][6]); FMA2(acc[1][6], w1, vd.x, acc[1][6]);
            FMA2(acc[2][6], w2, vd.x, acc[2][6]); FMA2(acc[3][6], w3, vd.x, acc[3][6]);
            FMA2(acc[0][7], w0, vd.y, acc[0][7]); FMA2(acc[1][7], w1, vd.y, acc[1][7]);
            FMA2(acc[2][7], w2, vd.y, acc[2][7]); FMA2(acc[3][7], w3, vd.y, acc[3][7]);
            Wp += IT;   // next j
            Vp += CB;
        }

        // ---- cross-jo reduce-scatter (2 shuffle rounds, proven pattern) ----
        {
            const bool hi3 = (l & 8) != 0;      // jo bit0
            ull keep0[8], keep1[8];
#pragma unroll
            for (int c = 0; c < 8; ++c) {
                ull s0 = hi3 ? acc[0][c] : acc[2][c];
                ull s1 = hi3 ? acc[1][c] : acc[3][c];
                ull r0 = __shfl_xor_sync(0xffffffffu, s0, 8);
                ull r1 = __shfl_xor_sync(0xffffffffu, s1, 8);
                ull k0 = hi3 ? acc[2][c] : acc[0][c];
                ull k1 = hi3 ? acc[3][c] : acc[1][c];
                ADD2(keep0[c], k0, r0);
                ADD2(keep1[c], k1, r1);
            }
            const bool hi4 = (l & 16) != 0;     // jo bit1
            const int rpo = ((l & 8) >> 2) | ((l & 16) >> 4);
#pragma unroll
            for (int c = 0; c < 8; ++c) {
                ull sd = hi4 ? keep0[c] : keep1[c];
                ull rv = __shfl_xor_sync(0xffffffffu, sd, 16);
                ull kp = hi4 ? keep1[c] : keep0[c];
                ull fin; ADD2(fin, kp, rv);
                red[(w * IT + rg * 4 + rpo) * RED_STRIDE + c] = fin;
            }
        }
        __syncthreads();

        // ---- final 8-warp reduction: this thread's own (row, colpair) ----
        ull sacc = red[(0 * IT + i_loc) * RED_STRIDE + lb];
#pragma unroll
        for (int ww = 1; ww < NW; ++ww)
            ADD2(sacc, sacc, red[(ww * IT + i_loc) * RED_STRIDE + lb]);

        // ---- state update for (b, h) ----
        {
            float Ccos, Csin;
            UNPACK2(Ccos, Csin, sacc);
            const float coup = s_sin * Ccos - s_cos * Csin;
            const float xv   = coup + p + s;
            const float k    = floorf(xv * INV_TWO_PI_F);
            float ns = fmaf(-TWO_PI_F, k, xv);
            if (ns < 0.0f) ns += TWO_PI_F;
            else if (ns >= TWO_PI_F) ns -= TWO_PI_F;
            s = ns;
            __sincosf(s, &s_sin, &s_cos);
            *(float2*)&d_V[ping ^ 1][bt][h][2 * lb] = make_float2(s_cos, s_sin);
        }
        ping ^= 1;

        // ---- publish via RED (atomic, L2-visible): this CTA finished step t ----
        __syncthreads();
        if (tid == 0) {
            __threadfence();
            atomicMax(&d_flags[bt][it], t + 1);   // unreturned -> RED.MAX at L2
        }
    }

    // ---- final state out + full-grid barrier + readout ----
    d_state[b * NH + h] = s;
    bar_on(&g_bar, GRID);

    if (cta == 0) {
        for (int pair = w; pair < BB * NO; pair += NW) {
            const int bb = pair / NO, oo = pair % NO;
            float acc = 0.0f;
            for (int hh = l; hh < NH; hh += 32)
                acc = fmaf(__ldcg(&d_state[bb * NH + hh]), W_out[(size_t)oo * NH + hh], acc);
#pragma unroll
            for (int off = 16; off; off >>= 1)
                acc += __shfl_down_sync(0xffffffffu, acc, off);
            if (l == 0) out[bb * NO + oo] = acc + b_out[oo];
        }
    }
}

extern "C" void kernel_launch(void* const* d_in, const int* in_sizes, int n_in,
                              void* d_out, int out_size) {
    const float* x     = (const float*)d_in[0];
    const float* Wi_w  = (const float*)d_in[1];
    const float* Wi_b  = (const float*)d_in[2];
    const float* Wh    = (const float*)d_in[3];
    const float* omega = (const float*)d_in[4];
    const float* W_out = (const float*)d_in[5];
    const float* b_out = (const float*)d_in[6];
    float* out = (float*)d_out;

    cudaFuncSetAttribute(scan_kernel, cudaFuncAttributeMaxDynamicSharedMemorySize, SMEM_BYTES);

    prep_kernel<<<T_STEPS * BB, 256>>>(x, Wi_w, Wi_b, omega);
    scan_kernel<<<GRID, NTH, SMEM_BYTES>>>(Wh, W_out, b_out, out);
}

// round 12
// speedup vs baseline: 1.1600x; 1.0848x over previous
#include <cuda_runtime.h>
#include <math.h>

#define T_STEPS 256
#define BB      32
#define NI      28
#define NH      1024
#define NO      10
#define GRID    128
#define NTH     256
#define NW      8         // warps per CTA
#define KS      128       // j-slice per warp
#define IT      32        // rows (i) per CTA
#define NBT     4         // batch tiles
#define CB      16        // V columns per CTA (8 batches x {cos,sin})
#define TWO_PI_F 6.283185307179586f
#define INV_TWO_PI_F 0.15915494309189535f

typedef unsigned long long ull;

// ---- persistent device scratch ----
__device__ float d_P[(size_t)T_STEPS * NH * BB];    // [t][h][b]
__device__ float d_V[2][NBT][NH][CB];               // [ping][btile][j][col]
__device__ float d_state[BB * NH];                  // [b][h]
__device__ int d_flags[NBT][32];                    // producer step counters (monotonic, RED-published)
__device__ unsigned g_bar;                          // final one-shot barrier

// packed f32x2 helpers
#define PACK2(d,a,b)   asm("mov.b64 %0, {%1, %2};" : "=l"(d) : "f"(a), "f"(b))
#define UNPACK2(a,b,v) asm("mov.b64 {%0, %1}, %2;" : "=f"(a), "=f"(b) : "l"(v))
#define FMA2(d,a,b,c)  asm("fma.rn.f32x2 %0, %1, %2, %3;" : "=l"(d) : "l"(a), "l"(b), "l"(c))
#define ADD2(d,a,b)    asm("add.rn.f32x2 %0, %1, %2;" : "=l"(d) : "l"(a), "l"(b))

// ---------------- prep ----------------
__global__ void prep_kernel(const float* __restrict__ x,
                            const float* __restrict__ Wi_w,
                            const float* __restrict__ Wi_b,
                            const float* __restrict__ omega) {
    const int bid = blockIdx.x;          // = t*BB + b
    const int t = bid >> 5;
    const int b = bid & 31;
    __shared__ float xs[NI];
    if (threadIdx.x < NI) xs[threadIdx.x] = x[(size_t)bid * NI + threadIdx.x];
    if (bid == 0) {
        if (threadIdx.x == 0) g_bar = 0u;
        if (threadIdx.x < NBT * 32) ((int*)d_flags)[threadIdx.x] = 0;
    }
    if (bid < (NBT * NH * CB) / 256) {
        const int idx = bid * 256 + threadIdx.x;
        ((float*)d_V)[idx] = (idx & 1) ? 0.0f : 1.0f;
    }
    __syncthreads();
#pragma unroll
    for (int k = 0; k < NH / 256; ++k) {
        const int h = threadIdx.x + k * 256;
        float acc = Wi_b[h] + omega[h];
        const float* wr = Wi_w + (size_t)h * NI;
#pragma unroll
        for (int i = 0; i < NI; ++i) acc = fmaf(xs[i], wr[i], acc);
        d_P[((size_t)t * NH + h) * BB + b] = acc;
    }
}

// ---------------- one-shot atomic barrier (final readout only) ----------------
__device__ __forceinline__ void bar_on(unsigned* ctr, unsigned target) {
    __syncthreads();
    if (threadIdx.x == 0) {
        __threadfence();
        atomicAdd(ctr, 1u);
        while (*(volatile unsigned*)ctr < target) { }
        __threadfence();
    }
    __syncthreads();
}

// ---------------- persistent scan kernel ----------------
// smem: WhT [1024][32] (128KB) | Vs [1024][16] (64KB) | red ull[8][32][9] padded (18KB)
#define RED_STRIDE 9
#define SMEM_FLOATS (NH*IT + NH*CB)
#define SMEM_BYTES  (SMEM_FLOATS*4 + NW*IT*RED_STRIDE*8)

extern __shared__ float smem[];

__global__ void __launch_bounds__(NTH, 1)
scan_kernel(const float* __restrict__ Wh,
            const float* __restrict__ W_out,
            const float* __restrict__ b_out,
            float* __restrict__ out) {
    float* WhT = smem;                          // WhT[j*32 + r] = Wh[i0+r][j]
    float* Vs  = smem + NH * IT;                // Vs[j*16 + c]
    ull*   red = (ull*)(smem + SMEM_FLOATS);    // red[(w*32+row)*9 + cp]

    const int tid = threadIdx.x;
    const int cta = blockIdx.x;
    const int it  = cta >> 2;            // i-tile 0..31
    const int bt  = cta & 3;             // batch-tile 0..3
    const int i0  = it * IT;

    // one-time fill of WhT (coalesced global reads)
    for (int idx = tid; idx < NH * IT; idx += NTH) {
        const int r = idx >> 10, j = idx & 1023;
        WhT[j * IT + r] = Wh[(size_t)(i0 + r) * NH + j];
    }

    const int w  = tid >> 5;             // warp: j-slice [w*128, w*128+128)
    const int l  = tid & 31;
    const int jo = l >> 3;               // 0..3 : j-offset group within a 32-row slice
    const int rg = l & 7;                // 0..7 : rows rg*4 .. rg*4+3

    const int i_loc = tid >> 3;          // 0..31
    const int lb    = tid & 7;           // 0..7
    const int h     = i0 + i_loc;
    const int b     = bt * 8 + lb;

    const unsigned vs_w = (unsigned)__cvta_generic_to_shared(Vs) + (unsigned)(w * KS * CB * 4);

    float s = 0.0f, s_sin = 0.0f, s_cos = 1.0f;

    __syncthreads();

    int ping = 0;

    for (int t = 0; t < T_STEPS; ++t) {
        const float p = __ldg(&d_P[((size_t)t * NH + h) * BB + b]);

        // producer-slice helpers (producer 4w+k owns j in [(4w+k)*32, +32))
        const char* vsrc_base = (const char*)(&d_V[ping][bt][0][0]) + (size_t)w * 8192;

        ull acc[4][8];
#pragma unroll
        for (int r = 0; r < 4; ++r)
#pragma unroll
            for (int c = 0; c < 8; ++c) acc[r][c] = 0ull;

#define WAIT_FLAG(k)                                                                     \
        {                                                                                \
            const int* fp = &d_flags[bt][w * 4 + (k)];                                   \
            int f;                                                                       \
            asm volatile("ld.global.cg.b32 %0, [%1];" : "=r"(f) : "l"(fp) : "memory");   \
            while (__any_sync(0xffffffffu, f < t)) {                                     \
                __nanosleep(20);                                                         \
                asm volatile("ld.global.cg.b32 %0, [%1];" : "=r"(f) : "l"(fp) : "memory");\
            }                                                                            \
        }

#define ISSUE_CP(k)                                                                      \
        {                                                                                \
            const char* src = vsrc_base + (k) * 2048 + l * 64;                           \
            unsigned dst = vs_w + (k) * 2048 + l * 64;                                   \
            asm volatile("cp.async.cg.shared.global [%0], [%1], 16;" :: "r"(dst),      "l"(src));      \
            asm volatile("cp.async.cg.shared.global [%0], [%1], 16;" :: "r"(dst + 16), "l"(src + 16)); \
            asm volatile("cp.async.cg.shared.global [%0], [%1], 16;" :: "r"(dst + 32), "l"(src + 32)); \
            asm volatile("cp.async.cg.shared.global [%0], [%1], 16;" :: "r"(dst + 48), "l"(src + 48)); \
            asm volatile("cp.async.commit_group;");                                      \
        }

#define GEMM_SLICE(k)                                                                    \
        {                                                                                \
            const float* Wp = WhT + (w * KS + (k) * 32 + jo * 8) * IT + rg * 4;          \
            const float* Vp = Vs  + (w * KS + (k) * 32 + jo * 8) * CB;                   \
            _Pragma("unroll")                                                            \
            for (int jj = 0; jj < 8; ++jj) {                                             \
                const float4 wv = *(const float4*)Wp;                                    \
                const ulonglong2 va = *(const ulonglong2*)Vp;                            \
                const ulonglong2 vb = *(const ulonglong2*)(Vp + 4);                      \
                const ulonglong2 vc = *(const ulonglong2*)(Vp + 8);                      \
                const ulonglong2 vd = *(const ulonglong2*)(Vp + 12);                     \
                ull w0, w1, w2, w3;                                                      \
                PACK2(w0, wv.x, wv.x); PACK2(w1, wv.y, wv.y);                            \
                PACK2(w2, wv.z, wv.z); PACK2(w3, wv.w, wv.w);                            \
                FMA2(acc[0][0], w0, va.x, acc[0][0]); FMA2(acc[1][0], w1, va.x, acc[1][0]); \
                FMA2(acc[2][0], w2, va.x, acc[2][0]); FMA2(acc[3][0], w3, va.x, acc[3][0]); \
                FMA2(acc[0][1], w0, va.y, acc[0][1]); FMA2(acc[1][1], w1, va.y, acc[1][1]); \
                FMA2(acc[2][1], w2, va.y, acc[2][1]); FMA2(acc[3][1], w3, va.y, acc[3][1]); \
                FMA2(acc[0][2], w0, vb.x, acc[0][2]); FMA2(acc[1][2], w1, vb.x, acc[1][2]); \
                FMA2(acc[2][2], w2, vb.x, acc[2][2]); FMA2(acc[3][2], w3, vb.x, acc[3][2]); \
                FMA2(acc[0][3], w0, vb.y, acc[0][3]); FMA2(acc[1][3], w1, vb.y, acc[1][3]); \
                FMA2(acc[2][3], w2, vb.y, acc[2][3]); FMA2(acc[3][3], w3, vb.y, acc[3][3]); \
                FMA2(acc[0][4], w0, vc.x, acc[0][4]); FMA2(acc[1][4], w1, vc.x, acc[1][4]); \
                FMA2(acc[2][4], w2, vc.x, acc[2][4]); FMA2(acc[3][4], w3, vc.x, acc[3][4]); \
                FMA2(acc[0][5], w0, vc.y, acc[0][5]); FMA2(acc[1][5], w1, vc.y, acc[1][5]); \
                FMA2(acc[2][5], w2, vc.y, acc[2][5]); FMA2(acc[3][5], w3, vc.y, acc[3][5]); \
                FMA2(acc[0][6], w0, vd.x, acc[0][6]); FMA2(acc[1][6], w1, vd.x, acc[1][6]); \
                FMA2(acc[2][6], w2, vd.x, acc[2][6]); FMA2(acc[3][6], w3, vd.x, acc[3][6]); \
                FMA2(acc[0][7], w0, vd.y, acc[0][7]); FMA2(acc[1][7], w1, vd.y, acc[1][7]); \
                FMA2(acc[2][7], w2, vd.y, acc[2][7]); FMA2(acc[3][7], w3, vd.y, acc[3][7]); \
                Wp += IT; Vp += CB;                                                      \
            }                                                                            \
        }

        // ---- pipelined wait/stage/GEMM over the 4 producer slices ----
        WAIT_FLAG(0); ISSUE_CP(0);
        WAIT_FLAG(1); ISSUE_CP(1);
        asm volatile("cp.async.wait_group 1;" ::: "memory"); __syncwarp();
        GEMM_SLICE(0);
        WAIT_FLAG(2); ISSUE_CP(2);
        asm volatile("cp.async.wait_group 1;" ::: "memory"); __syncwarp();
        GEMM_SLICE(1);
        WAIT_FLAG(3); ISSUE_CP(3);
        asm volatile("cp.async.wait_group 1;" ::: "memory"); __syncwarp();
        GEMM_SLICE(2);
        asm volatile("cp.async.wait_group 0;" ::: "memory"); __syncwarp();
        GEMM_SLICE(3);

        // ---- cross-jo reduce-scatter (2 shuffle rounds, proven pattern) ----
        {
            const bool hi3 = (l & 8) != 0;      // jo bit0
            ull keep0[8], keep1[8];
#pragma unroll
            for (int c = 0; c < 8; ++c) {
                ull s0 = hi3 ? acc[0][c] : acc[2][c];
                ull s1 = hi3 ? acc[1][c] : acc[3][c];
                ull r0 = __shfl_xor_sync(0xffffffffu, s0, 8);
                ull r1 = __shfl_xor_sync(0xffffffffu, s1, 8);
                ull k0 = hi3 ? acc[2][c] : acc[0][c];
                ull k1 = hi3 ? acc[3][c] : acc[1][c];
                ADD2(keep0[c], k0, r0);
                ADD2(keep1[c], k1, r1);
            }
            const bool hi4 = (l & 16) != 0;     // jo bit1
            const int rpo = ((l & 8) >> 2) | ((l & 16) >> 4);
#pragma unroll
            for (int c = 0; c < 8; ++c) {
                ull sd = hi4 ? keep0[c] : keep1[c];
                ull rv = __shfl_xor_sync(0xffffffffu, sd, 16);
                ull kp = hi4 ? keep1[c] : keep0[c];
                ull fin; ADD2(fin, kp, rv);
                red[(w * IT + rg * 4 + rpo) * RED_STRIDE + c] = fin;
            }
        }
        __syncthreads();

        // ---- final 8-warp reduction: this thread's own (row, colpair) ----
        ull sacc = red[(0 * IT + i_loc) * RED_STRIDE + lb];
#pragma unroll
        for (int ww = 1; ww < NW; ++ww)
            ADD2(sacc, sacc, red[(ww * IT + i_loc) * RED_STRIDE + lb]);

        // ---- state update for (b, h) ----
        {
            float Ccos, Csin;
            UNPACK2(Ccos, Csin, sacc);
            const float coup = s_sin * Ccos - s_cos * Csin;
            const float xv   = coup + p + s;
            const float k    = floorf(xv * INV_TWO_PI_F);
            float ns = fmaf(-TWO_PI_F, k, xv);
            if (ns < 0.0f) ns += TWO_PI_F;
            else if (ns >= TWO_PI_F) ns -= TWO_PI_F;
            s = ns;
            __sincosf(s, &s_sin, &s_cos);
            *(float2*)&d_V[ping ^ 1][bt][h][2 * lb] = make_float2(s_cos, s_sin);
        }
        ping ^= 1;

        // ---- publish via RED (atomic, L2-visible): this CTA finished step t ----
        __syncthreads();
        if (tid == 0) {
            __threadfence();
            atomicMax(&d_flags[bt][it], t + 1);   // unreturned -> RED.MAX at L2
        }
    }

    // ---- final state out + full-grid barrier + readout ----
    d_state[b * NH + h] = s;
    bar_on(&g_bar, GRID);

    if (cta == 0) {
        for (int pair = w; pair < BB * NO; pair += NW) {
            const int bb = pair / NO, oo = pair % NO;
            float acc = 0.0f;
            for (int hh = l; hh < NH; hh += 32)
                acc = fmaf(__ldcg(&d_state[bb * NH + hh]), W_out[(size_t)oo * NH + hh], acc);
#pragma unroll
            for (int off = 16; off; off >>= 1)
                acc += __shfl_down_sync(0xffffffffu, acc, off);
            if (l == 0) out[bb * NO + oo] = acc + b_out[oo];
        }
    }
}

extern "C" void kernel_launch(void* const* d_in, const int* in_sizes, int n_in,
                              void* d_out, int out_size) {
    const float* x     = (const float*)d_in[0];
    const float* Wi_w  = (const float*)d_in[1];
    const float* Wi_b  = (const float*)d_in[2];
    const float* Wh    = (const float*)d_in[3];
    const float* omega = (const float*)d_in[4];
    const float* W_out = (const float*)d_in[5];
    const float* b_out = (const float*)d_in[6];
    float* out = (float*)d_out;

    cudaFuncSetAttribute(scan_kernel, cudaFuncAttributeMaxDynamicSharedMemorySize, SMEM_BYTES);

    prep_kernel<<<T_STEPS * BB, 256>>>(x, Wi_w, Wi_b, omega);
    scan_kernel<<<GRID, NTH, SMEM_BYTES>>>(Wh, W_out, b_out, out);
}